// round 5
// baseline (speedup 1.0000x reference)
#include <cuda_runtime.h>
#include <cuda_bf16.h>
#include <cstdint>

#define BB 4
#define NN 50000
#define EE 800000

// ---------------------------------------------------------------------------
// Scratch. Node-major layout: row (n, b) at offset ((n*BB + b) * 32) floats,
// so one node's 4 batch rows are 512B contiguous (coalesced warp gathers).
// ---------------------------------------------------------------------------
__device__ float4 g_ya4[BB * NN * 8];   // ya = x@W1[0:32] + b1
__device__ float4 g_yb4[BB * NN * 8];   // yb = x@W1[32:64]
__device__ float4 g_acc4[BB * NN * 8];  // node accumulator (30 used, pad 32)
__device__ float  g_part[512];
__device__ float  g_stat[2];            // mean, rstd
__device__ int    g_is64;

typedef unsigned long long u64;

// ---- packed f32x2 helpers (sm_103a FFMA2 path; PTX-only) ----
__device__ __forceinline__ u64 pk2(float lo, float hi) {
    u64 r; asm("mov.b64 %0,{%1,%2};" : "=l"(r) : "f"(lo), "f"(hi)); return r;
}
__device__ __forceinline__ void upk2(float& lo, float& hi, u64 v) {
    asm("mov.b64 {%0,%1},%2;" : "=f"(lo), "=f"(hi) : "l"(v));
}
__device__ __forceinline__ u64 fma2(u64 a, u64 b, u64 c) {
    u64 d; asm("fma.rn.f32x2 %0,%1,%2,%3;" : "=l"(d) : "l"(a), "l"(b), "l"(c)); return d;
}
__device__ __forceinline__ u64 add2(u64 a, u64 b) {
    u64 d; asm("add.rn.f32x2 %0,%1,%2;" : "=l"(d) : "l"(a), "l"(b)); return d;
}

__device__ __forceinline__ float sigf(float x) {
    return __fdividef(1.0f, 1.0f + __expf(-x));
}
__device__ __forceinline__ float negf(float x) {
    return __int_as_float(__float_as_int(x) ^ 0x80000000);
}
__device__ __forceinline__ void red4(float* p, float a, float b, float c, float d) {
    asm volatile("red.global.add.v4.f32 [%0], {%1,%2,%3,%4};"
                 :: "l"(p), "f"(a), "f"(b), "f"(c), "f"(d) : "memory");
}

// ---------------------------------------------------------------------------
// 0. detect edge_index width
// ---------------------------------------------------------------------------
__global__ void k_detect(const void* ei) {
    const long long* p = (const long long*)ei;
    int ok64 = 1;
    for (int j = 0; j < 16; j++) {
        long long v = p[j];
        if (v < 0 || v >= (long long)NN) ok64 = 0;
    }
    g_is64 = ok64;
}

// ---------------------------------------------------------------------------
// 1. edge_attr stats (two-pass deterministic)
// ---------------------------------------------------------------------------
__global__ void k_stat1(const float* __restrict__ ea) {
    __shared__ float ss[256], sq[256];
    int tid = threadIdx.x;
    float s = 0.f, q = 0.f;
    for (int i = blockIdx.x * 256 + tid; i < EE; i += 256 * 256) {
        float v = __ldg(&ea[i]);
        s += v; q += v * v;
    }
    ss[tid] = s; sq[tid] = q;
    __syncthreads();
    for (int o = 128; o > 0; o >>= 1) {
        if (tid < o) { ss[tid] += ss[tid + o]; sq[tid] += sq[tid + o]; }
        __syncthreads();
    }
    if (tid == 0) {
        g_part[blockIdx.x]       = ss[0];
        g_part[256 + blockIdx.x] = sq[0];
    }
}

__global__ void k_stat2() {
    __shared__ float ss[256], sq[256];
    int tid = threadIdx.x;
    ss[tid] = g_part[tid];
    sq[tid] = g_part[256 + tid];
    __syncthreads();
    for (int o = 128; o > 0; o >>= 1) {
        if (tid < o) { ss[tid] += ss[tid + o]; sq[tid] += sq[tid + o]; }
        __syncthreads();
    }
    if (tid == 0) {
        float s = ss[0], q = sq[0];
        float mean = s / (float)EE;
        float var  = (q - s * s / (float)EE) / (float)(EE - 1);
        g_stat[0] = mean;
        g_stat[1] = rsqrtf(var);
    }
}

// ---------------------------------------------------------------------------
// 2. zero accumulator
// ---------------------------------------------------------------------------
__global__ void k_zero() {
    int i = blockIdx.x * blockDim.x + threadIdx.x;
    if (i < BB * NN * 8) g_acc4[i] = make_float4(0.f, 0.f, 0.f, 0.f);
}

// ---------------------------------------------------------------------------
// 3. precompute ya/yb, stored node-major (n*BB+b)
// ---------------------------------------------------------------------------
__global__ void __launch_bounds__(256) k_pre(const float* __restrict__ x,
                                             const float* __restrict__ W1,
                                             const float* __restrict__ b1) {
    int lane   = threadIdx.x & 31;
    int warp   = (blockIdx.x * blockDim.x + threadIdx.x) >> 5;
    int nwarps = (gridDim.x * blockDim.x) >> 5;

    u64 wab[32];
#pragma unroll
    for (int k = 0; k < 32; k++) {
        wab[k] = pk2(__ldg(&W1[k * 32 + lane]), __ldg(&W1[(32 + k) * 32 + lane]));
    }
    u64 binit = pk2(__ldg(&b1[lane]), 0.f);

    float* ya = reinterpret_cast<float*>(g_ya4);
    float* yb = reinterpret_cast<float*>(g_yb4);

    for (int row = warp; row < BB * NN; row += nwarps) {
        int b = row / NN;
        int n = row - b * NN;
        float xv = __ldg(&x[row * 32 + lane]);
        u64 acc = binit;
#pragma unroll
        for (int k = 0; k < 32; k++) {
            float xk = __shfl_sync(0xffffffffu, xv, k);
            acc = fma2(pk2(xk, xk), wab[k], acc);
        }
        float sa, sb;
        upk2(sa, sb, acc);
        int off = (n * BB + b) * 32 + lane;
        ya[off] = sa;
        yb[off] = sb;
    }
}

// ---------------------------------------------------------------------------
// 4. main edge kernel: WARP = edge; lane = (b = lane>>3, f4 = lane&7).
//    All gathers/scatters are 512B contiguous per warp (nL=4 per LDG/RED).
// ---------------------------------------------------------------------------
__global__ void __launch_bounds__(256) k_edge(const void* __restrict__ ei,
                                              const float* __restrict__ ea,
                                              const float* __restrict__ W1,
                                              const float* __restrict__ W2,
                                              const float* __restrict__ b2) {
    __shared__ ulonglong2 w1cp[8];     // W1 edge-attr row as 8 x (2 pairs)
    __shared__ ulonglong2 b2p[8];      // b2 padded, pairs
    __shared__ ulonglong2 w2p[32][8];  // W2[k] padded to 32 floats = 8 x 16B

    int tid = threadIdx.x;
    // stage weights
    for (int i = tid; i < 32 * 32; i += 256) {
        int k = i >> 5, j = i & 31;
        reinterpret_cast<float*>(w2p)[k * 32 + j] = (j < 30) ? W2[k * 30 + j] : 0.f;
    }
    if (tid < 32) {
        reinterpret_cast<float*>(w1cp)[tid] = W1[64 * 32 + tid];
        reinterpret_cast<float*>(b2p)[tid]  = (tid < 30) ? b2[tid] : 0.f;
    }
    __syncthreads();

    int e = (blockIdx.x * 256 + tid) >> 5;     // warp id = edge
    if (e >= EE) return;
    int lane = tid & 31;
    int f4   = lane & 7;

    int src, tgt;
    if (g_is64) {
        const long long* p = (const long long*)ei;
        src = (int)__ldg(&p[e]);
        tgt = (int)__ldg(&p[EE + e]);
    } else {
        const int* p = (const int*)ei;
        src = __ldg(&p[e]);
        tgt = __ldg(&p[EE + e]);
    }
    src = min(max(src, 0), NN - 1);
    tgt = min(max(tgt, 0), NN - 1);

    float ean = (__ldg(&ea[e]) - g_stat[0]) * g_stat[1];
    u64 ean2 = pk2(ean, ean);

    // gather: lane reads its 16B chunk; warp covers 512B contiguous per side
    const ulonglong2* pa = reinterpret_cast<const ulonglong2*>(g_ya4) + src * 32 + lane;
    const ulonglong2* pb = reinterpret_cast<const ulonglong2*>(g_yb4) + tgt * 32 + lane;
    ulonglong2 A = *pa;
    ulonglong2 C = *pb;

    ulonglong2 wc = w1cp[f4];
    u64 t0 = fma2(ean2, wc.x, add2(A.x, C.x));
    u64 t1 = fma2(ean2, wc.y, add2(A.y, C.y));

    float h1v[4];
    {
        float v0, v1, v2, v3;
        upk2(v0, v1, t0);
        upk2(v2, v3, t1);
        h1v[0] = sigf(v0); h1v[1] = sigf(v1);
        h1v[2] = sigf(v2); h1v[3] = sigf(v3);
    }

    // layer 2: lane owns outputs j = f4*4 .. f4*4+3
    ulonglong2 binit = b2p[f4];
    u64 acc0 = binit.x, acc1 = binit.y;
#pragma unroll
    for (int k = 0; k < 32; k++) {
        float h = __shfl_sync(0xffffffffu, h1v[k & 3], k >> 2, 8);  // within batch group
        u64 hh = pk2(h, h);
        ulonglong2 w = w2p[k][f4];
        acc0 = fma2(hh, w.x, acc0);
        acc1 = fma2(hh, w.y, acc1);
    }

    float s0, s1, s2, s3;
    upk2(s0, s1, acc0);
    upk2(s2, s3, acc1);
    s0 = sigf(s0); s1 = sigf(s1);
    if (f4 == 7) { s2 = 0.f; s3 = 0.f; }      // outputs 30,31 are padding
    else         { s2 = sigf(s2); s3 = sigf(s3); }

    // scatter: warp writes 512B contiguous per side
    float* at = reinterpret_cast<float*>(g_acc4) + tgt * 128 + lane * 4;
    float* as = reinterpret_cast<float*>(g_acc4) + src * 128 + lane * 4;
    red4(at, s0, s1, s2, s3);
    red4(as, negf(s0), negf(s1), negf(s2), negf(s3));
}

// ---------------------------------------------------------------------------
// 5. final: out = sigmoid(acc[:, :30] @ W3 + b3)   (warp per output row)
// ---------------------------------------------------------------------------
__global__ void __launch_bounds__(256) k_out(const float* __restrict__ W3,
                                             const float* __restrict__ b3,
                                             float* __restrict__ out) {
    int lane   = threadIdx.x & 31;
    int warp   = (blockIdx.x * blockDim.x + threadIdx.x) >> 5;
    int nwarps = (gridDim.x * blockDim.x) >> 5;

    float w3r[30];
#pragma unroll
    for (int k = 0; k < 30; k++) w3r[k] = __ldg(&W3[k * 32 + lane]);
    float bv = __ldg(&b3[lane]);

    const float* accf = reinterpret_cast<const float*>(g_acc4);

    for (int row = warp; row < BB * NN; row += nwarps) {
        int b = row / NN;
        int n = row - b * NN;
        float av = accf[(n * BB + b) * 32 + lane];
        float s = bv;
#pragma unroll
        for (int k = 0; k < 30; k++) {
            s = fmaf(__shfl_sync(0xffffffffu, av, k), w3r[k], s);
        }
        out[row * 32 + lane] = sigf(s);
    }
}

// ---------------------------------------------------------------------------
// launch: resolve inputs by element count (robust to metadata ordering).
// ---------------------------------------------------------------------------
extern "C" void kernel_launch(void* const* d_in, const int* in_sizes, int n_in,
                              void* d_out, int out_size) {
    const float *x = 0, *ea = 0, *W1 = 0, *b1 = 0, *W2 = 0, *b2 = 0, *W3 = 0, *b3 = 0;
    const void* ei = 0;
    int nW = 0, nb = 0;
    for (int i = 0; i < n_in; i++) {
        switch (in_sizes[i]) {
            case 6400000: x  = (const float*)d_in[i]; break;
            case 1600000: ei = d_in[i];               break;
            case 800000:  ea = (const float*)d_in[i]; break;
            case 2080:    W1 = (const float*)d_in[i]; break;
            case 960:     if (nW++ == 0) W2 = (const float*)d_in[i];
                          else           W3 = (const float*)d_in[i]; break;
            case 32:      if (nb++ == 0) b1 = (const float*)d_in[i];
                          else           b3 = (const float*)d_in[i]; break;
            case 30:      b2 = (const float*)d_in[i]; break;
        }
    }
    float* out = (float*)d_out;

    k_detect<<<1, 1>>>(ei);
    k_stat1<<<256, 256>>>(ea);
    k_stat2<<<1, 256>>>();
    k_zero<<<(BB * NN * 8 + 255) / 256, 256>>>();
    k_pre<<<512, 256>>>(x, W1, b1);

    k_edge<<<(EE * 32 + 255) / 256, 256>>>(ei, ea, W1, W2, b2);

    k_out<<<512, 256>>>(W3, b3, out);
}